// round 6
// baseline (speedup 1.0000x reference)
#include <cuda_runtime.h>

#define NN 100000
#define EE 3200000
#define FF 128
#define HH 16
#define NCHUNK ((NN + 255) / 256)   // 391

// ---- static device scratch ----
__device__ int   g_cnt[NN];
__device__ int   g_off[NN];         // after fill: g_off[i] = end_i
__device__ int   g_bsum[NCHUNK];
__device__ int   g_bpre[NCHUNK];
__device__ int   g_csr[EE];
__device__ float g_dis[NN];
__device__ float g_u[NN * HH];      // (x @ W1) * dis[node]
__device__ float g_v[NN];
__device__ int            g_bar_count;
__device__ volatile int   g_bar_gen;

__device__ __forceinline__ void grid_barrier(int nb) {
    __syncthreads();
    if (threadIdx.x == 0) {
        __threadfence();
        int gen = g_bar_gen;
        if (atomicAdd(&g_bar_count, 1) == nb - 1) {
            g_bar_count = 0;
            __threadfence();
            g_bar_gen = gen + 1;
        } else {
            while (g_bar_gen == gen) __nanosleep(64);
        }
    }
    __syncthreads();
}

__global__ __launch_bounds__(256, 8)
void k_all(const float* __restrict__ x, const int* __restrict__ ei,
           const float* __restrict__ W1, const float* __restrict__ b1,
           const float* __restrict__ W2, const float* __restrict__ b2,
           float* __restrict__ out, int nb) {
    const int tid = threadIdx.x;
    const int gid0 = blockIdx.x * 256 + tid;
    const int stride = nb * 256;
    const int* src = ei;
    const int* dst = ei + EE;

    __shared__ int   sh[256];
    __shared__ int   s2[512];
    __shared__ float Wsh[FF * HH];      // 8 KB
    __shared__ float xsh[16 * 132];     // 16 rows padded to 132 floats

    // ---- P0: zero counters ----
    for (int i = gid0; i < NN; i += stride) g_cnt[i] = 0;
    grid_barrier(nb);

    // ---- P1: in-degree count ----
    for (int e = gid0; e < EE; e += stride) atomicAdd(&g_cnt[dst[e]], 1);
    grid_barrier(nb);

    // ---- P2: per-256-chunk exclusive scan ----
    for (int c = blockIdx.x; c < NCHUNK; c += nb) {
        int i = c * 256 + tid;
        int v = (i < NN) ? g_cnt[i] : 0;
        sh[tid] = v;
        __syncthreads();
        for (int d = 1; d < 256; d <<= 1) {
            int t = (tid >= d) ? sh[tid - d] : 0;
            __syncthreads();
            sh[tid] += t;
            __syncthreads();
        }
        if (i < NN) g_off[i] = sh[tid] - v;
        if (tid == 255) g_bsum[c] = sh[255];
        __syncthreads();
    }
    grid_barrier(nb);

    // ---- P3: block 0 scans the 391 chunk sums (512-wide Hillis-Steele) ----
    if (blockIdx.x == 0) {
        int v0 = (tid < NCHUNK) ? g_bsum[tid] : 0;
        int v1 = (256 + tid < NCHUNK) ? g_bsum[256 + tid] : 0;
        s2[tid] = v0; s2[256 + tid] = v1;
        __syncthreads();
        for (int d = 1; d < 512; d <<= 1) {
            int a = (tid >= d) ? s2[tid - d] : 0;
            int b = (256 + tid >= d) ? s2[256 + tid - d] : 0;
            __syncthreads();
            s2[tid] += a; s2[256 + tid] += b;
            __syncthreads();
        }
        if (tid < NCHUNK) g_bpre[tid] = s2[tid] - v0;
        if (256 + tid < NCHUNK) g_bpre[256 + tid] = s2[256 + tid] - v1;
    }
    grid_barrier(nb);

    // ---- P4: finalize offsets + dis ----
    for (int i = gid0; i < NN; i += stride) {
        g_off[i] += g_bpre[i >> 8];
        g_dis[i] = rsqrtf((float)(g_cnt[i] + 1));
    }
    grid_barrier(nb);

    // ---- P5: CSR fill (bump g_off in place -> end offsets) ----
    for (int e = gid0; e < EE; e += stride) {
        int p = atomicAdd(&g_off[dst[e]], 1);
        g_csr[p] = src[e];
    }
    // (no barrier: P6 is independent of P5)

    // ---- P6: gemm  u[i,:] = (x[i,:] @ W1) * dis[i] ----
    for (int k = tid; k < FF * HH; k += 256) Wsh[k] = W1[k];
    __syncthreads();
    for (int n0 = blockIdx.x * 16; n0 < NN; n0 += nb * 16) {   // NN % 16 == 0
        const float4* xv = (const float4*)(x + (size_t)n0 * FF);
        __syncthreads();
        for (int idx = tid; idx < 16 * 32; idx += 256) {
            int row = idx >> 5, col = idx & 31;
            *(float4*)&xsh[row * 132 + col * 4] = xv[row * 32 + col];
        }
        __syncthreads();
        int r = tid >> 4, h = tid & 15;
        int node = n0 + r;
        float acc = 0.f;
#pragma unroll 16
        for (int k = 0; k < FF; k++) acc += xsh[r * 132 + k] * Wsh[k * HH + h];
        g_u[node * HH + h] = acc * g_dis[node];
    }
    grid_barrier(nb);

    // ---- P7: layer-1 aggregate + relu + W2 projection (4 lanes / node, float4) ----
    {
        int gq = gid0 >> 2;          // group id
        int qh = tid & 3;            // which float4 of the 16-wide row
        int ngroups = stride >> 2;
        const float4* u4 = (const float4*)g_u;
        float4 bb = ((const float4*)b1)[qh];
        float4 ww = ((const float4*)W2)[qh];
        for (int node = gq; node < NN; node += ngroups) {
            int beg = node ? g_off[node - 1] : 0;
            int end = g_off[node];
            float4 acc = make_float4(0.f, 0.f, 0.f, 0.f);
            for (int e = beg; e < end; e++) {
                int s = g_csr[e];
                float4 t = u4[s * 4 + qh];
                acc.x += t.x; acc.y += t.y; acc.z += t.z; acc.w += t.w;
            }
            float4 us = u4[node * 4 + qh];
            acc.x += us.x; acc.y += us.y; acc.z += us.z; acc.w += us.w;
            float dis = g_dis[node];
            float p = fmaxf(fmaf(dis, acc.x, bb.x), 0.f) * ww.x
                    + fmaxf(fmaf(dis, acc.y, bb.y), 0.f) * ww.y
                    + fmaxf(fmaf(dis, acc.z, bb.z), 0.f) * ww.z
                    + fmaxf(fmaf(dis, acc.w, bb.w), 0.f) * ww.w;
            p += __shfl_xor_sync(0xFFFFFFFFu, p, 1, 4);
            p += __shfl_xor_sync(0xFFFFFFFFu, p, 2, 4);
            if (qh == 0) g_v[node] = dis * p;
        }
    }
    grid_barrier(nb);

    // ---- P8: layer-2 aggregate -> output (one warp / node) ----
    {
        int warp = gid0 >> 5, lane = tid & 31, nwarp = stride >> 5;
        float bias = b2[0];
        for (int node = warp; node < NN; node += nwarp) {
            int beg = node ? g_off[node - 1] : 0;
            int end = g_off[node];
            float acc = 0.f;
            for (int e = beg + lane; e < end; e += 32) acc += g_v[g_csr[e]];
#pragma unroll
            for (int d = 16; d >= 1; d >>= 1)
                acc += __shfl_down_sync(0xFFFFFFFFu, acc, d);
            if (lane == 0) out[node] = g_dis[node] * (acc + g_v[node]) + bias;
        }
    }
}

extern "C" void kernel_launch(void* const* d_in, const int* in_sizes, int n_in,
                              void* d_out, int out_size) {
    const float* x  = (const float*)d_in[0];
    const int*   ei = (const int*)d_in[1];
    const float* W1 = (const float*)d_in[2];
    const float* b1 = (const float*)d_in[3];
    const float* W2 = (const float*)d_in[4];
    const float* b2 = (const float*)d_in[5];
    float* out = (float*)d_out;

    // Exactly-resident grid, computed once on the uncaptured correctness call.
    static int nb = 0;
    if (!nb) {
        int dev = 0, nsm = 0, per = 0;
        cudaGetDevice(&dev);
        cudaDeviceGetAttribute(&nsm, cudaDevAttrMultiProcessorCount, dev);
        cudaOccupancyMaxActiveBlocksPerMultiprocessor(&per, k_all, 256, 0);
        if (per < 1) per = 1;
        nb = nsm * per;
    }

    k_all<<<nb, 256>>>(x, ei, W1, b1, W2, b2, out, nb);
}